// round 1
// baseline (speedup 1.0000x reference)
#include <cuda_runtime.h>
#include <math.h>
#include <stdint.h>

#define BB 2
#define SS 2048
#define HH 1024
#define NH 16
#define HD 64
#define BH 32
#define NROWS 4096

// scratch (static __device__ arrays are allowed; no runtime allocation)
__device__ float g_q[(size_t)BH * SS * HD];
__device__ float g_k[(size_t)BH * SS * HD];
__device__ float g_v[(size_t)BH * SS * HD];
__device__ float g_kt[(size_t)BH * HD * SS];   // K transposed: [bh][d][s]

// ---------------------------------------------------------------------------
// Projection GEMM: out = X @ W^T + b, scattered to [bh][s][d] layout.
// BM=128, BN=64, BK=16, 256 threads, 8x4 register micro-tile.
// ---------------------------------------------------------------------------
__global__ __launch_bounds__(256) void proj_kernel(
    const float* __restrict__ X, const float* __restrict__ W,
    const float* __restrict__ bias, float* __restrict__ outp)
{
    __shared__ float As[16][128];   // [k][row]
    __shared__ float Ws[16][64];    // [k][col]
    const int tid = threadIdx.x;
    const int tx = tid & 15;        // col group (4 cols)
    const int ty = tid >> 4;        // row group (8 rows)
    const int i0 = blockIdx.y * 128;
    const int j0 = blockIdx.x * 64;

    float acc[8][4];
#pragma unroll
    for (int i = 0; i < 8; i++)
#pragma unroll
        for (int j = 0; j < 4; j++) acc[i][j] = 0.f;

    for (int k0 = 0; k0 < HH; k0 += 16) {
        // A tile: 128 rows x 16 k -> 512 float4, 2 per thread
#pragma unroll
        for (int e = 0; e < 2; e++) {
            int f = tid * 2 + e;
            int r = f >> 2, c4 = f & 3;
            float4 v = *(const float4*)(X + (size_t)(i0 + r) * HH + k0 + c4 * 4);
            As[c4 * 4 + 0][r] = v.x; As[c4 * 4 + 1][r] = v.y;
            As[c4 * 4 + 2][r] = v.z; As[c4 * 4 + 3][r] = v.w;
        }
        // W tile: 64 rows x 16 k -> 256 float4, 1 per thread
        {
            int r = tid >> 2, c4 = tid & 3;
            float4 v = *(const float4*)(W + (size_t)(j0 + r) * HH + k0 + c4 * 4);
            Ws[c4 * 4 + 0][r] = v.x; Ws[c4 * 4 + 1][r] = v.y;
            Ws[c4 * 4 + 2][r] = v.z; Ws[c4 * 4 + 3][r] = v.w;
        }
        __syncthreads();
#pragma unroll
        for (int kk = 0; kk < 16; kk++) {
            float4 a0 = *(const float4*)&As[kk][ty * 8];
            float4 a1 = *(const float4*)&As[kk][ty * 8 + 4];
            float4 w4 = *(const float4*)&Ws[kk][tx * 4];
            float av[8] = {a0.x, a0.y, a0.z, a0.w, a1.x, a1.y, a1.z, a1.w};
#pragma unroll
            for (int i = 0; i < 8; i++) {
                acc[i][0] += av[i] * w4.x;
                acc[i][1] += av[i] * w4.y;
                acc[i][2] += av[i] * w4.z;
                acc[i][3] += av[i] * w4.w;
            }
        }
        __syncthreads();
    }

    float4 bb = *(const float4*)(bias + j0 + tx * 4);
    const int cidx = j0 + tx * 4;
    const int hh = cidx >> 6;          // head
    const int dd = cidx & 63;          // dim within head
#pragma unroll
    for (int i = 0; i < 8; i++) {
        int r = i0 + ty * 8 + i;       // = b*S + s
        int b = r >> 11, s = r & 2047;
        float4 o;
        o.x = acc[i][0] + bb.x; o.y = acc[i][1] + bb.y;
        o.z = acc[i][2] + bb.z; o.w = acc[i][3] + bb.w;
        *(float4*)(outp + (((size_t)(b * NH + hh)) * SS + s) * HD + dd) = o;
    }
}

// ---------------------------------------------------------------------------
// Transpose K: [bh][s][d] -> [bh][d][s]  (so score tiles load conflict-free)
// ---------------------------------------------------------------------------
__global__ __launch_bounds__(256) void transpose_kernel(
    const float* __restrict__ in, float* __restrict__ outp)
{
    __shared__ float t[32][33];
    const int bh = blockIdx.z;
    const int s0 = blockIdx.x * 32;
    const int d0 = blockIdx.y * 32;
    const int x = threadIdx.x, y = threadIdx.y;   // 32 x 8
    const float* ip = in + ((size_t)bh * SS + s0) * HD + d0;
    for (int i = y; i < 32; i += 8) t[i][x] = ip[(size_t)i * HD + x];
    __syncthreads();
    float* op = outp + ((size_t)bh * HD + d0) * SS + s0;
    for (int i = y; i < 32; i += 8) op[(size_t)i * SS + x] = t[x][i];
}

// ---------------------------------------------------------------------------
// Fused attention: scores + softmax(T=0.5) + threshold prune + L1 renorm
//                  + weights write + PV GEMM + out write.
// One block = one (b,h) x 16 q-rows. Full 16x2048 score strip in smem.
// Prune math: w_j = e_j/Z >= theta  <=>  e_j >= theta*Z;  final = e_j/S_kept.
// ---------------------------------------------------------------------------
#define QT 16
#define KT 128
#define ATTN_SMEM ((QT * SS + HD * KT + QT * HD) * 4 + SS)

__global__ __launch_bounds__(256) void attn_kernel(
    const unsigned char* __restrict__ mask,
    float* __restrict__ outp, float* __restrict__ wout)
{
    extern __shared__ float sm[];
    float* sc = sm;                          // [QT][SS] scores/weights strip
    float* kts = sm + QT * SS;               // [HD][KT] K^T tile (reused as V tile)
    float* qt = kts + HD * KT;               // [QT][HD]
    unsigned char* msk = (unsigned char*)(qt + QT * HD);   // [SS]

    const int tid = threadIdx.x;
    const int bh = blockIdx.y;
    const int b = bh >> 4, h = bh & 15;
    const int q0 = blockIdx.x * QT;
    const int qg = tid >> 5;   // warp id: owns q rows 2*qg, 2*qg+1
    const int kg = tid & 31;   // lane

    const float* Qp = g_q + ((size_t)bh * SS + q0) * HD;
    const float* Ktp = g_kt + (size_t)bh * HD * SS;
    const float* Vp = g_v + (size_t)bh * SS * HD;

    // load Q tile (16x64)
    {
        int r = tid >> 4, c4 = tid & 15;
        *(float4*)&qt[r * HD + c4 * 4] = *(const float4*)(Qp + (size_t)r * HD + c4 * 4);
    }
    // load padding mask for this batch
    {
        const uint32_t* mp = (const uint32_t*)(mask + (size_t)b * SS);
        uint32_t* md = (uint32_t*)msk;
        for (int i = tid; i < SS / 4; i += 256) md[i] = mp[i];
    }
    __syncthreads();

    // ---- Phase 1: scores (logits already scaled by 1/(sqrt(d)*T) = 0.25) ----
    for (int kc = 0; kc < SS; kc += KT) {
        // K^T tile: kts[kk][0..127] <- Kt[bh][kk][kc..kc+127]  (conflict-free)
#pragma unroll
        for (int e = 0; e < 8; e++) {
            int f = e * 256 + tid;
            int kk = f >> 5, c = f & 31;
            *(float4*)&kts[kk * KT + c * 4] =
                *(const float4*)(Ktp + (size_t)kk * SS + kc + c * 4);
        }
        __syncthreads();

        float acc0[4] = {0, 0, 0, 0};
        float acc1[4] = {0, 0, 0, 0};
#pragma unroll
        for (int k4 = 0; k4 < 16; k4++) {
            float4 qa = *(const float4*)&qt[(2 * qg) * HD + k4 * 4];
            float4 qb = *(const float4*)&qt[(2 * qg + 1) * HD + k4 * 4];
            float qav[4] = {qa.x, qa.y, qa.z, qa.w};
            float qbv[4] = {qb.x, qb.y, qb.z, qb.w};
#pragma unroll
            for (int j = 0; j < 4; j++) {
                float4 kv = *(const float4*)&kts[(k4 * 4 + j) * KT + kg * 4];
                acc0[0] += qav[j] * kv.x; acc0[1] += qav[j] * kv.y;
                acc0[2] += qav[j] * kv.z; acc0[3] += qav[j] * kv.w;
                acc1[0] += qbv[j] * kv.x; acc1[1] += qbv[j] * kv.y;
                acc1[2] += qbv[j] * kv.z; acc1[3] += qbv[j] * kv.w;
            }
        }
        const unsigned char* m4 = &msk[kc + kg * 4];
        float4 ra, rb;
        ra.x = m4[0] ? -1e30f : acc0[0] * 0.25f;
        ra.y = m4[1] ? -1e30f : acc0[1] * 0.25f;
        ra.z = m4[2] ? -1e30f : acc0[2] * 0.25f;
        ra.w = m4[3] ? -1e30f : acc0[3] * 0.25f;
        rb.x = m4[0] ? -1e30f : acc1[0] * 0.25f;
        rb.y = m4[1] ? -1e30f : acc1[1] * 0.25f;
        rb.z = m4[2] ? -1e30f : acc1[2] * 0.25f;
        rb.w = m4[3] ? -1e30f : acc1[3] * 0.25f;
        *(float4*)&sc[(2 * qg) * SS + kc + kg * 4] = ra;
        *(float4*)&sc[(2 * qg + 1) * SS + kc + kg * 4] = rb;
        __syncthreads();
    }

    // ---- Phase 2: per-row softmax + prune + renorm, write weights ----
    // warp qg handles rows qg and qg+8 (warp-private, no extra syncs needed)
#pragma unroll
    for (int rr = 0; rr < 2; rr++) {
        const int qi = qg + rr * 8;
        float* row = sc + qi * SS;
        float mx = -3.0e38f;
        for (int i = kg; i < SS; i += 32) mx = fmaxf(mx, row[i]);
#pragma unroll
        for (int o = 16; o; o >>= 1) mx = fmaxf(mx, __shfl_xor_sync(0xffffffffu, mx, o));
        float z = 0.f;
        for (int i = kg; i < SS; i += 32) {
            float e = __expf(row[i] - mx);
            row[i] = e;
            z += e;
        }
#pragma unroll
        for (int o = 16; o; o >>= 1) z += __shfl_xor_sync(0xffffffffu, z, o);
        const float cut = 0.01f * z;   // keep iff e >= theta*Z  (<=> w >= theta)
        float sk = 0.f;
        for (int i = kg; i < SS; i += 32) {
            float e = row[i];
            if (e >= cut) sk += e;
        }
#pragma unroll
        for (int o = 16; o; o >>= 1) sk += __shfl_xor_sync(0xffffffffu, sk, o);
        const float inv = sk > 0.f ? 1.f / sk : 0.f;   // all-pruned row -> zeros
        float4* row4 = (float4*)row;
        float4* wr4 = (float4*)(wout + ((size_t)bh * SS + q0 + qi) * SS);
        for (int i = kg; i < SS / 4; i += 32) {
            float4 e4 = row4[i];
            float4 w4;
            w4.x = e4.x >= cut ? e4.x * inv : 0.f;
            w4.y = e4.y >= cut ? e4.y * inv : 0.f;
            w4.z = e4.z >= cut ? e4.z * inv : 0.f;
            w4.w = e4.w >= cut ? e4.w * inv : 0.f;
            row4[i] = w4;
            wr4[i] = w4;
        }
    }
    __syncthreads();

    // ---- Phase 3: out = weights @ V ----
    float o00 = 0.f, o01 = 0.f, o10 = 0.f, o11 = 0.f;
    const int dg = kg;                 // cols dg*2, dg*2+1
    float* vt = kts;                   // reuse tile buffer: [KT][HD]
    for (int vc = 0; vc < SS; vc += KT) {
#pragma unroll
        for (int e = 0; e < 8; e++) {
            int f = e * 256 + tid;
            int r = f >> 4, c4 = f & 15;
            *(float4*)&vt[r * HD + c4 * 4] =
                *(const float4*)(Vp + (size_t)(vc + r) * HD + c4 * 4);
        }
        __syncthreads();
#pragma unroll
        for (int k4 = 0; k4 < KT / 4; k4++) {
            float4 wa = *(const float4*)&sc[(2 * qg) * SS + vc + k4 * 4];
            float4 wb = *(const float4*)&sc[(2 * qg + 1) * SS + vc + k4 * 4];
            float wav[4] = {wa.x, wa.y, wa.z, wa.w};
            float wbv[4] = {wb.x, wb.y, wb.z, wb.w};
#pragma unroll
            for (int j = 0; j < 4; j++) {
                float2 v = *(const float2*)&vt[(k4 * 4 + j) * HD + dg * 2];
                o00 += wav[j] * v.x; o01 += wav[j] * v.y;
                o10 += wbv[j] * v.x; o11 += wbv[j] * v.y;
            }
        }
        __syncthreads();
    }
    {
        int r0 = q0 + 2 * qg;
        float2 u0 = make_float2(o00, o01);
        float2 u1 = make_float2(o10, o11);
        *(float2*)(outp + ((size_t)b * SS + r0) * HH + h * HD + dg * 2) = u0;
        *(float2*)(outp + ((size_t)b * SS + r0 + 1) * HH + h * HD + dg * 2) = u1;
    }
}

// ---------------------------------------------------------------------------
extern "C" void kernel_launch(void* const* d_in, const int* in_sizes, int n_in,
                              void* d_out, int out_size)
{
    const float* query = (const float*)d_in[0];
    const float* key   = (const float*)d_in[1];
    const float* value = (const float*)d_in[2];
    const unsigned char* mask = (const unsigned char*)d_in[3];
    const float* Wq = (const float*)d_in[4];
    const float* bq = (const float*)d_in[5];
    const float* Wk = (const float*)d_in[6];
    const float* bk = (const float*)d_in[7];
    const float* Wv = (const float*)d_in[8];
    const float* bv = (const float*)d_in[9];

    float* outp = (float*)d_out;                        // [B,S,H]
    float* wts  = outp + (size_t)BB * SS * HH;          // [B,h,S,S]

    float *gq, *gk, *gv, *gkt;
    cudaGetSymbolAddress((void**)&gq, g_q);
    cudaGetSymbolAddress((void**)&gk, g_k);
    cudaGetSymbolAddress((void**)&gv, g_v);
    cudaGetSymbolAddress((void**)&gkt, g_kt);

    cudaFuncSetAttribute(attn_kernel, cudaFuncAttributeMaxDynamicSharedMemorySize,
                         ATTN_SMEM);

    dim3 pgrid(HH / 64, NROWS / 128);
    proj_kernel<<<pgrid, 256>>>(query, Wq, bq, gq);
    proj_kernel<<<pgrid, 256>>>(key,   Wk, bk, gk);
    proj_kernel<<<pgrid, 256>>>(value, Wv, bv, gv);

    dim3 tgrid(SS / 32, HD / 32, BH);
    transpose_kernel<<<tgrid, dim3(32, 8)>>>(gk, gkt);

    dim3 agrid(SS / QT, BH);
    attn_kernel<<<agrid, 256, ATTN_SMEM>>>(mask, outp, wts);
}

// round 2
// speedup vs baseline: 1.5400x; 1.5400x over previous
#include <cuda_runtime.h>
#include <math.h>
#include <stdint.h>

#define BB 2
#define SS 2048
#define HH 1024
#define NH 16
#define HD 64
#define BH 32
#define NROWS 4096

// scratch (static __device__ arrays; no runtime allocation)
__device__ float g_q[(size_t)BH * SS * HD];
__device__ float g_k[(size_t)BH * SS * HD];
__device__ float g_v[(size_t)BH * SS * HD];
__device__ float g_kt[(size_t)BH * HD * SS];   // K transposed: [bh][d][s]
__device__ float g_wt[(size_t)HH * HH];        // current W transposed: [k][n]

typedef unsigned long long u64;

// ---- packed fp32x2 helpers (sm_103a FFMA2) ----
__device__ __forceinline__ u64 bcast2(float x) {
    u64 d; unsigned int u = __float_as_uint(x);
    asm("mov.b64 %0, {%1,%2};" : "=l"(d) : "r"(u), "r"(u));
    return d;
}
__device__ __forceinline__ u64 ffma2(u64 a, u64 b, u64 c) {
    u64 d;
    asm("fma.rn.f32x2 %0, %1, %2, %3;" : "=l"(d) : "l"(a), "l"(b), "l"(c));
    return d;
}
__device__ __forceinline__ float2 unpk(u64 v) {
    unsigned int lo, hi;
    asm("mov.b64 {%0,%1}, %2;" : "=r"(lo), "=r"(hi) : "l"(v));
    return make_float2(__uint_as_float(lo), __uint_as_float(hi));
}
__device__ __forceinline__ float f4c(const float4& v, int i) {
    return i == 0 ? v.x : i == 1 ? v.y : i == 2 ? v.z : v.w;
}

// ---------------------------------------------------------------------------
// Generic 1024x1024 transpose (for W matrices): out[k][n] = in[n][k]
// ---------------------------------------------------------------------------
__global__ __launch_bounds__(256) void transpose_w(
    const float* __restrict__ in, float* __restrict__ outp)
{
    __shared__ float t[32][33];
    const int x0 = blockIdx.x * 32, y0 = blockIdx.y * 32;
    const int x = threadIdx.x, y = threadIdx.y;   // 32 x 8
    for (int i = y; i < 32; i += 8) t[i][x] = in[(size_t)(y0 + i) * HH + x0 + x];
    __syncthreads();
    for (int i = y; i < 32; i += 8) outp[(size_t)(x0 + i) * HH + y0 + x] = t[x][i];
}

// ---------------------------------------------------------------------------
// Transpose K: [bh][s][d] -> [bh][d][s]
// ---------------------------------------------------------------------------
__global__ __launch_bounds__(256) void transpose_k(
    const float* __restrict__ in, float* __restrict__ outp)
{
    __shared__ float t[32][33];
    const int bh = blockIdx.z;
    const int s0 = blockIdx.x * 32;
    const int d0 = blockIdx.y * 32;
    const int x = threadIdx.x, y = threadIdx.y;   // 32 x 8
    const float* ip = in + ((size_t)bh * SS + s0) * HD + d0;
    for (int i = y; i < 32; i += 8) t[i][x] = ip[(size_t)i * HD + x];
    __syncthreads();
    float* op = outp + ((size_t)bh * HD + d0) * SS + s0;
    for (int i = y; i < 32; i += 8) op[(size_t)i * SS + x] = t[x][i];
}

// ---------------------------------------------------------------------------
// Projection GEMM: out = X @ W^T + b  (W pre-transposed to [k][n] in g_wt),
// scattered to [bh][s][d]. Tile 128x128, BK=16, thread 8x8, FFMA2.
// ---------------------------------------------------------------------------
#define APAD 20

__global__ __launch_bounds__(256) void proj_kernel(
    const float* __restrict__ X, const float* __restrict__ Wt,
    const float* __restrict__ bias, float* __restrict__ outp)
{
    __shared__ float As[128 * APAD];   // [row][k] row-major, pad to 20
    __shared__ float Bs[16 * 128];     // [k][col]
    const int tid = threadIdx.x;
    const int tx = tid & 15;           // col group (8 cols)
    const int ty = tid >> 4;           // row group (8 rows)
    const int i0 = blockIdx.y * 128;
    const int j0 = blockIdx.x * 128;

    u64 acc[8][4];
#pragma unroll
    for (int i = 0; i < 8; i++)
#pragma unroll
        for (int j = 0; j < 4; j++) acc[i][j] = 0ull;

    for (int k0 = 0; k0 < HH; k0 += 16) {
#pragma unroll
        for (int e = 0; e < 2; e++) {
            int f = e * 256 + tid;
            int r = f >> 2, c4 = f & 3;
            *(float4*)&As[r * APAD + c4 * 4] =
                *(const float4*)(X + (size_t)(i0 + r) * HH + k0 + c4 * 4);
        }
#pragma unroll
        for (int e = 0; e < 2; e++) {
            int f = e * 256 + tid;
            int k = f >> 5, c = f & 31;
            *(float4*)&Bs[k * 128 + c * 4] =
                *(const float4*)(Wt + (size_t)(k0 + k) * HH + j0 + c * 4);
        }
        __syncthreads();
#pragma unroll
        for (int k4 = 0; k4 < 4; k4++) {
            float4 aq[8];
#pragma unroll
            for (int i = 0; i < 8; i++)
                aq[i] = *(const float4*)&As[(ty * 8 + i) * APAD + k4 * 4];
#pragma unroll
            for (int dd = 0; dd < 4; dd++) {
                const float* bp = &Bs[(k4 * 4 + dd) * 128 + tx * 8];
                ulonglong2 b0 = *(const ulonglong2*)bp;
                ulonglong2 b1 = *(const ulonglong2*)(bp + 4);
#pragma unroll
                for (int i = 0; i < 8; i++) {
                    u64 ap = bcast2(f4c(aq[i], dd));
                    acc[i][0] = ffma2(ap, b0.x, acc[i][0]);
                    acc[i][1] = ffma2(ap, b0.y, acc[i][1]);
                    acc[i][2] = ffma2(ap, b1.x, acc[i][2]);
                    acc[i][3] = ffma2(ap, b1.y, acc[i][3]);
                }
            }
        }
        __syncthreads();
    }

    const int col = j0 + tx * 8;
    const int h = col >> 6, d = col & 63;
    float4 bb0 = *(const float4*)(bias + col);
    float4 bb1 = *(const float4*)(bias + col + 4);
#pragma unroll
    for (int i = 0; i < 8; i++) {
        int r = i0 + ty * 8 + i;
        int b = r >> 11, s = r & 2047;
        float2 p0 = unpk(acc[i][0]), p1 = unpk(acc[i][1]);
        float2 p2 = unpk(acc[i][2]), p3 = unpk(acc[i][3]);
        float4 o0 = make_float4(p0.x + bb0.x, p0.y + bb0.y, p1.x + bb0.z, p1.y + bb0.w);
        float4 o1 = make_float4(p2.x + bb1.x, p2.y + bb1.y, p3.x + bb1.z, p3.y + bb1.w);
        float* op = outp + (((size_t)(b * NH + h)) * SS + s) * HD + d;
        *(float4*)op = o0;
        *(float4*)(op + 4) = o1;
    }
}

// ---------------------------------------------------------------------------
// Score GEMM: wout[bh][i][j] = 0.25 * sum_d q[i,d]*k[j,d]. Tile 128x128, K=64
// fully resident in smem. Q row-major (broadcast a-reads), K^T [d][j].
// ---------------------------------------------------------------------------
#define QPAD 68
#define SCORE_SMEM ((64 * 128 + 128 * QPAD) * 4)

__global__ __launch_bounds__(256) void score_kernel(float* __restrict__ wout)
{
    extern __shared__ float sm[];
    float* Ks = sm;                 // [64][128]
    float* Qs = sm + 64 * 128;      // [128][QPAD]
    const int tid = threadIdx.x;
    const int tx = tid & 15, ty = tid >> 4;
    const int bh = blockIdx.z;
    const int i0 = blockIdx.y * 128;
    const int j0 = blockIdx.x * 128;

    // load Q tile [128][64] row-major
#pragma unroll
    for (int e = 0; e < 8; e++) {
        int f = e * 256 + tid;
        int r = f >> 4, c4 = f & 15;
        *(float4*)&Qs[r * QPAD + c4 * 4] =
            *(const float4*)(g_q + ((size_t)bh * SS + i0 + r) * HD + c4 * 4);
    }
    // load K^T tile [64][128]
#pragma unroll
    for (int e = 0; e < 8; e++) {
        int f = e * 256 + tid;
        int d = f >> 5, c = f & 31;
        *(float4*)&Ks[d * 128 + c * 4] =
            *(const float4*)(g_kt + ((size_t)bh * HD + d) * SS + j0 + c * 4);
    }
    __syncthreads();

    u64 acc[8][4];
#pragma unroll
    for (int i = 0; i < 8; i++)
#pragma unroll
        for (int j = 0; j < 4; j++) acc[i][j] = 0ull;

#pragma unroll 4
    for (int d4 = 0; d4 < 16; d4++) {
        float4 aq[8];
#pragma unroll
        for (int i = 0; i < 8; i++)
            aq[i] = *(const float4*)&Qs[(ty * 8 + i) * QPAD + d4 * 4];
#pragma unroll
        for (int dd = 0; dd < 4; dd++) {
            const float* bp = &Ks[(d4 * 4 + dd) * 128 + tx * 8];
            ulonglong2 b0 = *(const ulonglong2*)bp;
            ulonglong2 b1 = *(const ulonglong2*)(bp + 4);
#pragma unroll
            for (int i = 0; i < 8; i++) {
                u64 ap = bcast2(f4c(aq[i], dd));
                acc[i][0] = ffma2(ap, b0.x, acc[i][0]);
                acc[i][1] = ffma2(ap, b0.y, acc[i][1]);
                acc[i][2] = ffma2(ap, b1.x, acc[i][2]);
                acc[i][3] = ffma2(ap, b1.y, acc[i][3]);
            }
        }
    }

#pragma unroll
    for (int i = 0; i < 8; i++) {
        float2 p0 = unpk(acc[i][0]), p1 = unpk(acc[i][1]);
        float2 p2 = unpk(acc[i][2]), p3 = unpk(acc[i][3]);
        float4 o0 = make_float4(p0.x * 0.25f, p0.y * 0.25f, p1.x * 0.25f, p1.y * 0.25f);
        float4 o1 = make_float4(p2.x * 0.25f, p2.y * 0.25f, p3.x * 0.25f, p3.y * 0.25f);
        float* op = wout + ((size_t)bh * SS + i0 + ty * 8 + i) * SS + j0 + tx * 8;
        *(float4*)op = o0;
        *(float4*)(op + 4) = o1;
    }
}

// ---------------------------------------------------------------------------
// Row softmax(T folded into scores) + threshold prune + L1 renorm, in place.
// One warp per row; 2048 floats live in 64 registers per lane.
// Prune: w = e/Z >= theta  <=>  e >= theta*Z; final = e / S_kept.
// ---------------------------------------------------------------------------
__global__ __launch_bounds__(256) void softmax_kernel(
    const unsigned char* __restrict__ mask, float* __restrict__ w)
{
    const int lane = threadIdx.x & 31;
    const size_t row = (size_t)blockIdx.x * 8 + (threadIdx.x >> 5);
    const int b = (int)(row >> 15);                  // bh = row>>11, b = bh>>4
    float4* rp = (float4*)(w + row * SS);
    const uchar4* mp = (const uchar4*)(mask + (size_t)b * SS);

    float x[64];
    float mx = -3.0e38f;
#pragma unroll
    for (int v = 0; v < 16; v++) {
        float4 t = rp[lane + v * 32];
        uchar4 m = mp[lane + v * 32];
        x[v * 4 + 0] = m.x ? -1e30f : t.x;
        x[v * 4 + 1] = m.y ? -1e30f : t.y;
        x[v * 4 + 2] = m.z ? -1e30f : t.z;
        x[v * 4 + 3] = m.w ? -1e30f : t.w;
    }
#pragma unroll
    for (int i = 0; i < 64; i++) mx = fmaxf(mx, x[i]);
#pragma unroll
    for (int o = 16; o; o >>= 1) mx = fmaxf(mx, __shfl_xor_sync(0xffffffffu, mx, o));

    float z = 0.f;
#pragma unroll
    for (int i = 0; i < 64; i++) {
        float e = __expf(x[i] - mx);
        x[i] = e;
        z += e;
    }
#pragma unroll
    for (int o = 16; o; o >>= 1) z += __shfl_xor_sync(0xffffffffu, z, o);

    const float cut = 0.01f * z;
    float sk = 0.f;
#pragma unroll
    for (int i = 0; i < 64; i++)
        if (x[i] >= cut) sk += x[i];
#pragma unroll
    for (int o = 16; o; o >>= 1) sk += __shfl_xor_sync(0xffffffffu, sk, o);
    const float inv = sk > 0.f ? 1.f / sk : 0.f;

#pragma unroll
    for (int v = 0; v < 16; v++) {
        float4 o4;
        o4.x = x[v * 4 + 0] >= cut ? x[v * 4 + 0] * inv : 0.f;
        o4.y = x[v * 4 + 1] >= cut ? x[v * 4 + 1] * inv : 0.f;
        o4.z = x[v * 4 + 2] >= cut ? x[v * 4 + 2] * inv : 0.f;
        o4.w = x[v * 4 + 3] >= cut ? x[v * 4 + 3] * inv : 0.f;
        rp[lane + v * 32] = o4;
    }
}

// ---------------------------------------------------------------------------
// PV GEMM: out[b][s][h*64+d] = sum_j W[bh][i][j] * V[bh][j][d].
// Tile 128 rows x 64 cols, k-chunk 32, thread 8x4, FFMA2.
// ---------------------------------------------------------------------------
#define WPAD 36

__global__ __launch_bounds__(256) void pv_kernel(
    const float* __restrict__ wts, float* __restrict__ outp)
{
    __shared__ float Wt[128 * WPAD];   // [row][j], pad 36
    __shared__ float Vt[32 * 64];      // [j][d]
    const int tid = threadIdx.x;
    const int tx = tid & 15;           // col group (4 cols over 64)
    const int ty = tid >> 4;           // row group (8 rows)
    const int bh = blockIdx.y;
    const int b = bh >> 4, h = bh & 15;
    const int i0 = blockIdx.x * 128;
    const float* Wp = wts + ((size_t)bh * SS + i0) * SS;
    const float* Vp = g_v + (size_t)bh * SS * HD;

    u64 acc[8][2];
#pragma unroll
    for (int i = 0; i < 8; i++) { acc[i][0] = 0ull; acc[i][1] = 0ull; }

    for (int kc = 0; kc < SS; kc += 32) {
#pragma unroll
        for (int e = 0; e < 4; e++) {
            int f = e * 256 + tid;
            int r = f >> 3, c4 = f & 7;
            *(float4*)&Wt[r * WPAD + c4 * 4] =
                *(const float4*)(Wp + (size_t)r * SS + kc + c4 * 4);
        }
#pragma unroll
        for (int e = 0; e < 2; e++) {
            int f = e * 256 + tid;
            int j = f >> 4, c4 = f & 15;
            *(float4*)&Vt[j * 64 + c4 * 4] =
                *(const float4*)(Vp + (size_t)(kc + j) * HD + c4 * 4);
        }
        __syncthreads();
#pragma unroll
        for (int j4 = 0; j4 < 8; j4++) {
            float4 aw[8];
#pragma unroll
            for (int i = 0; i < 8; i++)
                aw[i] = *(const float4*)&Wt[(ty * 8 + i) * WPAD + j4 * 4];
#pragma unroll
            for (int dd = 0; dd < 4; dd++) {
                ulonglong2 bv = *(const ulonglong2*)&Vt[(j4 * 4 + dd) * 64 + tx * 4];
#pragma unroll
                for (int i = 0; i < 8; i++) {
                    u64 ap = bcast2(f4c(aw[i], dd));
                    acc[i][0] = ffma2(ap, bv.x, acc[i][0]);
                    acc[i][1] = ffma2(ap, bv.y, acc[i][1]);
                }
            }
        }
        __syncthreads();
    }

#pragma unroll
    for (int i = 0; i < 8; i++) {
        float2 p0 = unpk(acc[i][0]), p1 = unpk(acc[i][1]);
        float4 o4 = make_float4(p0.x, p0.y, p1.x, p1.y);
        int s = i0 + ty * 8 + i;
        *(float4*)(outp + ((size_t)b * SS + s) * HH + h * HD + tx * 4) = o4;
    }
}

// ---------------------------------------------------------------------------
extern "C" void kernel_launch(void* const* d_in, const int* in_sizes, int n_in,
                              void* d_out, int out_size)
{
    const float* query = (const float*)d_in[0];
    const float* key   = (const float*)d_in[1];
    const float* value = (const float*)d_in[2];
    const unsigned char* mask = (const unsigned char*)d_in[3];
    const float* Wq = (const float*)d_in[4];
    const float* bq = (const float*)d_in[5];
    const float* Wk = (const float*)d_in[6];
    const float* bk = (const float*)d_in[7];
    const float* Wv = (const float*)d_in[8];
    const float* bv = (const float*)d_in[9];

    float* outp = (float*)d_out;                        // [B,S,H]
    float* wts  = outp + (size_t)BB * SS * HH;          // [B,h,S,S]

    float *gq, *gk, *gv, *gkt, *gwt;
    cudaGetSymbolAddress((void**)&gq, g_q);
    cudaGetSymbolAddress((void**)&gk, g_k);
    cudaGetSymbolAddress((void**)&gv, g_v);
    cudaGetSymbolAddress((void**)&gkt, g_kt);
    cudaGetSymbolAddress((void**)&gwt, g_wt);

    cudaFuncSetAttribute(score_kernel, cudaFuncAttributeMaxDynamicSharedMemorySize,
                         SCORE_SMEM);

    dim3 tw(32, 32);
    dim3 tb(32, 8);
    dim3 pgrid(HH / 128, NROWS / 128);

    transpose_w<<<tw, tb>>>(Wq, gwt);
    proj_kernel<<<pgrid, 256>>>(query, gwt, bq, gq);
    transpose_w<<<tw, tb>>>(Wk, gwt);
    proj_kernel<<<pgrid, 256>>>(key, gwt, bk, gk);
    transpose_w<<<tw, tb>>>(Wv, gwt);
    proj_kernel<<<pgrid, 256>>>(value, gwt, bv, gv);

    dim3 tkgrid(SS / 32, HD / 32, BH);
    transpose_k<<<tkgrid, tb>>>(gk, gkt);

    dim3 sgrid(SS / 128, SS / 128, BH);
    score_kernel<<<sgrid, 256, SCORE_SMEM>>>(wts);

    softmax_kernel<<<(BH * SS) / 8, 256>>>(mask, wts);

    dim3 vgrid(SS / 128, BH);
    pv_kernel<<<vgrid, 256>>>(wts, outp);
}

// round 3
// speedup vs baseline: 1.7044x; 1.1067x over previous
#include <cuda_runtime.h>
#include <math.h>
#include <stdint.h>

#define BB 2
#define SS 2048
#define HH 1024
#define NH 16
#define HD 64
#define BH 32
#define NROWS 4096

// scratch (static __device__ arrays; no runtime allocation)
__device__ float g_q[(size_t)BH * SS * HD];
__device__ float g_k[(size_t)BH * SS * HD];
__device__ float g_v[(size_t)BH * SS * HD];
__device__ float g_kt[(size_t)BH * HD * SS];      // K transposed: [bh][d][s]
__device__ float g_wt[3 * (size_t)HH * HH];       // Wq,Wk,Wv transposed: [k][n]

typedef unsigned long long u64;

// ---- packed fp32x2 helpers (sm_103a FFMA2) ----
__device__ __forceinline__ u64 bcast2(float x) {
    u64 d; unsigned int u = __float_as_uint(x);
    asm("mov.b64 %0, {%1,%2};" : "=l"(d) : "r"(u), "r"(u));
    return d;
}
__device__ __forceinline__ u64 ffma2(u64 a, u64 b, u64 c) {
    u64 d;
    asm("fma.rn.f32x2 %0, %1, %2, %3;" : "=l"(d) : "l"(a), "l"(b), "l"(c));
    return d;
}
__device__ __forceinline__ float2 unpk(u64 v) {
    unsigned int lo, hi;
    asm("mov.b64 {%0,%1}, %2;" : "=r"(lo), "=r"(hi) : "l"(v));
    return make_float2(__uint_as_float(lo), __uint_as_float(hi));
}
__device__ __forceinline__ float f4c(const float4& v, int i) {
    return i == 0 ? v.x : i == 1 ? v.y : i == 2 ? v.z : v.w;
}

// ---- cp.async helpers ----
__device__ __forceinline__ void cpa16(void* s, const void* g) {
    unsigned int sa = (unsigned int)__cvta_generic_to_shared(s);
    asm volatile("cp.async.ca.shared.global [%0], [%1], 16;" :: "r"(sa), "l"(g));
}
#define CPA_COMMIT  asm volatile("cp.async.commit_group;")
#define CPA_WAIT1   asm volatile("cp.async.wait_group 1;")
#define CPA_WAIT0   asm volatile("cp.async.wait_group 0;")

// ---------------------------------------------------------------------------
// Transpose all three W matrices: g_wt[z][k][n] = W_z[n][k]
// ---------------------------------------------------------------------------
__global__ __launch_bounds__(256) void transpose_w3(
    const float* __restrict__ Wq, const float* __restrict__ Wk,
    const float* __restrict__ Wv, float* __restrict__ outp)
{
    __shared__ float t[32][33];
    const int z = blockIdx.z;
    const float* in = z == 0 ? Wq : z == 1 ? Wk : Wv;
    float* op = outp + (size_t)z * HH * HH;
    const int x0 = blockIdx.x * 32, y0 = blockIdx.y * 32;
    const int x = threadIdx.x, y = threadIdx.y;   // 32 x 8
    for (int i = y; i < 32; i += 8) t[i][x] = in[(size_t)(y0 + i) * HH + x0 + x];
    __syncthreads();
    for (int i = y; i < 32; i += 8) op[(size_t)(x0 + i) * HH + y0 + x] = t[x][i];
}

// ---------------------------------------------------------------------------
// Transpose K: [bh][s][d] -> [bh][d][s]
// ---------------------------------------------------------------------------
__global__ __launch_bounds__(256) void transpose_k(
    const float* __restrict__ in, float* __restrict__ outp)
{
    __shared__ float t[32][33];
    const int bh = blockIdx.z;
    const int s0 = blockIdx.x * 32;
    const int d0 = blockIdx.y * 32;
    const int x = threadIdx.x, y = threadIdx.y;   // 32 x 8
    const float* ip = in + ((size_t)bh * SS + s0) * HD + d0;
    for (int i = y; i < 32; i += 8) t[i][x] = ip[(size_t)i * HD + x];
    __syncthreads();
    float* op = outp + ((size_t)bh * HD + d0) * SS + s0;
    for (int i = y; i < 32; i += 8) op[(size_t)i * SS + x] = t[x][i];
}

// ---------------------------------------------------------------------------
// Fused QKV projection GEMM (grid.z selects q/k/v): out = X @ W^T + b,
// scattered to [bh][s][d]. Tile 128x128, BK=16, 8x8 FFMA2 micro-tile,
// 2-stage cp.async double buffering.
// ---------------------------------------------------------------------------
#define APAD 20
#define PROJ_STAGE (128 * APAD + 16 * 128)   // floats per stage

__global__ __launch_bounds__(256) void proj_kernel(
    const float* __restrict__ Xq, const float* __restrict__ Xk,
    const float* __restrict__ Xv, const float* __restrict__ Wt3,
    const float* __restrict__ bq, const float* __restrict__ bk,
    const float* __restrict__ bv,
    float* __restrict__ oq, float* __restrict__ ok, float* __restrict__ ov)
{
    __shared__ float sm[2 * PROJ_STAGE];
    const int z = blockIdx.z;
    const float* X    = z == 0 ? Xq : z == 1 ? Xk : Xv;
    const float* Wt   = Wt3 + (size_t)z * HH * HH;
    const float* bias = z == 0 ? bq : z == 1 ? bk : bv;
    float* outp       = z == 0 ? oq : z == 1 ? ok : ov;

    const int tid = threadIdx.x;
    const int tx = tid & 15;           // col group (8 cols)
    const int ty = tid >> 4;           // row group (8 rows)
    const int i0 = blockIdx.y * 128;
    const int j0 = blockIdx.x * 128;

    // prefetch helper (issues 3 cp.async per thread + commit)
    auto prefetch = [&](int k0, int buf) {
        float* As = sm + buf * PROJ_STAGE;
        float* Bs = As + 128 * APAD;
#pragma unroll
        for (int e = 0; e < 2; e++) {
            int f = e * 256 + tid;
            int r = f >> 2, c4 = f & 3;
            cpa16(&As[r * APAD + c4 * 4], X + (size_t)(i0 + r) * HH + k0 + c4 * 4);
        }
        {
            int f = tid;
            int k = f >> 5, c = f & 31;
            cpa16(&Bs[k * 128 + c * 4], Wt + (size_t)(k0 + k) * HH + j0 + c * 4);
            f = 256 + tid;
            k = f >> 5; c = f & 31;
            cpa16(&Bs[k * 128 + c * 4], Wt + (size_t)(k0 + k) * HH + j0 + c * 4);
        }
        CPA_COMMIT;
    };

    u64 acc[8][4];
#pragma unroll
    for (int i = 0; i < 8; i++)
#pragma unroll
        for (int j = 0; j < 4; j++) acc[i][j] = 0ull;

    prefetch(0, 0);

    for (int it = 0; it < 64; it++) {
        if (it < 63) { prefetch((it + 1) * 16, (it + 1) & 1); CPA_WAIT1; }
        else         { CPA_WAIT0; }
        __syncthreads();
        const float* As = sm + (it & 1) * PROJ_STAGE;
        const float* Bs = As + 128 * APAD;
#pragma unroll
        for (int k4 = 0; k4 < 4; k4++) {
            float4 aq[8];
#pragma unroll
            for (int i = 0; i < 8; i++)
                aq[i] = *(const float4*)&As[(ty * 8 + i) * APAD + k4 * 4];
#pragma unroll
            for (int dd = 0; dd < 4; dd++) {
                const float* bp = &Bs[(k4 * 4 + dd) * 128 + tx * 8];
                ulonglong2 b0 = *(const ulonglong2*)bp;
                ulonglong2 b1 = *(const ulonglong2*)(bp + 4);
#pragma unroll
                for (int i = 0; i < 8; i++) {
                    u64 ap = bcast2(f4c(aq[i], dd));
                    acc[i][0] = ffma2(ap, b0.x, acc[i][0]);
                    acc[i][1] = ffma2(ap, b0.y, acc[i][1]);
                    acc[i][2] = ffma2(ap, b1.x, acc[i][2]);
                    acc[i][3] = ffma2(ap, b1.y, acc[i][3]);
                }
            }
        }
        __syncthreads();
    }

    const int col = j0 + tx * 8;
    const int h = col >> 6, d = col & 63;
    float4 bb0 = *(const float4*)(bias + col);
    float4 bb1 = *(const float4*)(bias + col + 4);
#pragma unroll
    for (int i = 0; i < 8; i++) {
        int r = i0 + ty * 8 + i;
        int b = r >> 11, s = r & 2047;
        float2 p0 = unpk(acc[i][0]), p1 = unpk(acc[i][1]);
        float2 p2 = unpk(acc[i][2]), p3 = unpk(acc[i][3]);
        float4 o0 = make_float4(p0.x + bb0.x, p0.y + bb0.y, p1.x + bb0.z, p1.y + bb0.w);
        float4 o1 = make_float4(p2.x + bb1.x, p2.y + bb1.y, p3.x + bb1.z, p3.y + bb1.w);
        float* op = outp + (((size_t)(b * NH + h)) * SS + s) * HD + d;
        *(float4*)op = o0;
        *(float4*)(op + 4) = o1;
    }
}

// ---------------------------------------------------------------------------
// Score GEMM: wout[bh][i][j] = 0.25 * sum_d q[i,d]*k[j,d].
// Block = 128 i-rows x (4 consecutive 128-wide j-tiles). Q tile loaded once,
// K^T tiles double-buffered with cp.async.
// ---------------------------------------------------------------------------
#define QPAD 68
#define KSTAGE (64 * 128)
#define SCORE_SMEM ((128 * QPAD + 2 * KSTAGE) * 4)

__global__ void score_kernel(float* __restrict__ wout)
{
    extern __shared__ float sm[];
    float* Qs = sm;                       // [128][QPAD]
    float* Kbuf = sm + 128 * QPAD;        // 2 x [64][128]
    const int tid = threadIdx.x;
    const int tx = tid & 15, ty = tid >> 4;
    const int bh = blockIdx.z;
    const int i0 = blockIdx.y * 128;
    const int jb0 = blockIdx.x * 4;

    const float* Qp = g_q + ((size_t)bh * SS + i0) * HD;
    const float* Ktp = g_kt + (size_t)bh * HD * SS;

    // group 0: Q tile [128][64]
#pragma unroll
    for (int e = 0; e < 8; e++) {
        int f = e * 256 + tid;
        int r = f >> 4, c4 = f & 15;
        cpa16(&Qs[r * QPAD + c4 * 4], Qp + (size_t)r * HD + c4 * 4);
    }
    CPA_COMMIT;

    auto prefetchK = [&](int j0, int buf) {
        float* Ks = Kbuf + buf * KSTAGE;
#pragma unroll
        for (int e = 0; e < 8; e++) {
            int f = e * 256 + tid;
            int d = f >> 5, c = f & 31;
            cpa16(&Ks[d * 128 + c * 4], Ktp + (size_t)d * SS + j0 + c * 4);
        }
        CPA_COMMIT;
    };
    prefetchK(jb0 * 128, 0);

    for (int jt = 0; jt < 4; jt++) {
        const int j0 = (jb0 + jt) * 128;
        if (jt < 3) { prefetchK(j0 + 128, (jt + 1) & 1); CPA_WAIT1; }
        else        { CPA_WAIT0; }
        __syncthreads();
        const float* Ks = Kbuf + (jt & 1) * KSTAGE;

        u64 acc[8][4];
#pragma unroll
        for (int i = 0; i < 8; i++)
#pragma unroll
            for (int j = 0; j < 4; j++) acc[i][j] = 0ull;

#pragma unroll 4
        for (int d4 = 0; d4 < 16; d4++) {
            float4 aq[8];
#pragma unroll
            for (int i = 0; i < 8; i++)
                aq[i] = *(const float4*)&Qs[(ty * 8 + i) * QPAD + d4 * 4];
#pragma unroll
            for (int dd = 0; dd < 4; dd++) {
                const float* bp = &Ks[(d4 * 4 + dd) * 128 + tx * 8];
                ulonglong2 b0 = *(const ulonglong2*)bp;
                ulonglong2 b1 = *(const ulonglong2*)(bp + 4);
#pragma unroll
                for (int i = 0; i < 8; i++) {
                    u64 ap = bcast2(f4c(aq[i], dd));
                    acc[i][0] = ffma2(ap, b0.x, acc[i][0]);
                    acc[i][1] = ffma2(ap, b0.y, acc[i][1]);
                    acc[i][2] = ffma2(ap, b1.x, acc[i][2]);
                    acc[i][3] = ffma2(ap, b1.y, acc[i][3]);
                }
            }
        }

#pragma unroll
        for (int i = 0; i < 8; i++) {
            float2 p0 = unpk(acc[i][0]), p1 = unpk(acc[i][1]);
            float2 p2 = unpk(acc[i][2]), p3 = unpk(acc[i][3]);
            float4 o0 = make_float4(p0.x * 0.25f, p0.y * 0.25f, p1.x * 0.25f, p1.y * 0.25f);
            float4 o1 = make_float4(p2.x * 0.25f, p2.y * 0.25f, p3.x * 0.25f, p3.y * 0.25f);
            float* op = wout + ((size_t)bh * SS + i0 + ty * 8 + i) * SS + j0 + tx * 8;
            *(float4*)op = o0;
            *(float4*)(op + 4) = o1;
        }
        __syncthreads();
    }
}

// ---------------------------------------------------------------------------
// Row softmax + threshold prune + L1 renorm, in place (exact fp32 path).
// One warp per row; 2048 floats in 64 regs/lane.
// ---------------------------------------------------------------------------
__global__ __launch_bounds__(256) void softmax_kernel(
    const unsigned char* __restrict__ mask, float* __restrict__ w)
{
    const int lane = threadIdx.x & 31;
    const size_t row = (size_t)blockIdx.x * 8 + (threadIdx.x >> 5);
    const int b = (int)(row >> 15);
    float4* rp = (float4*)(w + row * SS);
    const uchar4* mp = (const uchar4*)(mask + (size_t)b * SS);

    float x[64];
    float mx = -3.0e38f;
#pragma unroll
    for (int v = 0; v < 16; v++) {
        float4 t = rp[lane + v * 32];
        uchar4 m = mp[lane + v * 32];
        x[v * 4 + 0] = m.x ? -1e30f : t.x;
        x[v * 4 + 1] = m.y ? -1e30f : t.y;
        x[v * 4 + 2] = m.z ? -1e30f : t.z;
        x[v * 4 + 3] = m.w ? -1e30f : t.w;
    }
#pragma unroll
    for (int i = 0; i < 64; i++) mx = fmaxf(mx, x[i]);
#pragma unroll
    for (int o = 16; o; o >>= 1) mx = fmaxf(mx, __shfl_xor_sync(0xffffffffu, mx, o));

    float z = 0.f;
#pragma unroll
    for (int i = 0; i < 64; i++) {
        float e = __expf(x[i] - mx);
        x[i] = e;
        z += e;
    }
#pragma unroll
    for (int o = 16; o; o >>= 1) z += __shfl_xor_sync(0xffffffffu, z, o);

    const float cut = 0.01f * z;
    float sk = 0.f;
#pragma unroll
    for (int i = 0; i < 64; i++)
        if (x[i] >= cut) sk += x[i];
#pragma unroll
    for (int o = 16; o; o >>= 1) sk += __shfl_xor_sync(0xffffffffu, sk, o);
    const float inv = sk > 0.f ? 1.f / sk : 0.f;

#pragma unroll
    for (int v = 0; v < 16; v++) {
        float4 o4;
        o4.x = x[v * 4 + 0] >= cut ? x[v * 4 + 0] * inv : 0.f;
        o4.y = x[v * 4 + 1] >= cut ? x[v * 4 + 1] * inv : 0.f;
        o4.z = x[v * 4 + 2] >= cut ? x[v * 4 + 2] * inv : 0.f;
        o4.w = x[v * 4 + 3] >= cut ? x[v * 4 + 3] * inv : 0.f;
        rp[lane + v * 32] = o4;
    }
}

// ---------------------------------------------------------------------------
// PV GEMM: out[b][s][h*64+d] = sum_j W[bh][i][j] * V[bh][j][d].
// Tile 128 x 64, k-chunk 32, 8x4 FFMA2 micro-tile, 2-stage cp.async.
// ---------------------------------------------------------------------------
#define WPAD 36
#define PV_STAGE (128 * WPAD + 32 * 64)
#define PV_SMEM (2 * PV_STAGE * 4)

__global__ __launch_bounds__(256, 2) void pv_kernel(
    const float* __restrict__ wts, float* __restrict__ outp)
{
    extern __shared__ float psm[];
    const int tid = threadIdx.x;
    const int tx = tid & 15;           // col group (4 cols over 64)
    const int ty = tid >> 4;           // row group (8 rows)
    const int bh = blockIdx.y;
    const int b = bh >> 4, h = bh & 15;
    const int i0 = blockIdx.x * 128;
    const float* Wp = wts + ((size_t)bh * SS + i0) * SS;
    const float* Vp = g_v + (size_t)bh * SS * HD;

    auto prefetch = [&](int kc, int buf) {
        float* Wt = psm + buf * PV_STAGE;
        float* Vt = Wt + 128 * WPAD;
#pragma unroll
        for (int e = 0; e < 4; e++) {
            int f = e * 256 + tid;
            int r = f >> 3, c4 = f & 7;
            cpa16(&Wt[r * WPAD + c4 * 4], Wp + (size_t)r * SS + kc + c4 * 4);
        }
        {
            int f = tid;
            int j = f >> 4, c4 = f & 15;
            cpa16(&Vt[j * 64 + c4 * 4], Vp + (size_t)(kc + j) * HD + c4 * 4);
            f = 256 + tid;
            j = f >> 4; c4 = f & 15;
            cpa16(&Vt[j * 64 + c4 * 4], Vp + (size_t)(kc + j) * HD + c4 * 4);
        }
        CPA_COMMIT;
    };

    u64 acc[8][2];
#pragma unroll
    for (int i = 0; i < 8; i++) { acc[i][0] = 0ull; acc[i][1] = 0ull; }

    prefetch(0, 0);

    for (int it = 0; it < 64; it++) {
        if (it < 63) { prefetch((it + 1) * 32, (it + 1) & 1); CPA_WAIT1; }
        else         { CPA_WAIT0; }
        __syncthreads();
        const float* Wt = psm + (it & 1) * PV_STAGE;
        const float* Vt = Wt + 128 * WPAD;
#pragma unroll
        for (int j4 = 0; j4 < 8; j4++) {
            float4 aw[8];
#pragma unroll
            for (int i = 0; i < 8; i++)
                aw[i] = *(const float4*)&Wt[(ty * 8 + i) * WPAD + j4 * 4];
#pragma unroll
            for (int dd = 0; dd < 4; dd++) {
                ulonglong2 bv = *(const ulonglong2*)&Vt[(j4 * 4 + dd) * 64 + tx * 4];
#pragma unroll
                for (int i = 0; i < 8; i++) {
                    u64 ap = bcast2(f4c(aw[i], dd));
                    acc[i][0] = ffma2(ap, bv.x, acc[i][0]);
                    acc[i][1] = ffma2(ap, bv.y, acc[i][1]);
                }
            }
        }
        __syncthreads();
    }

#pragma unroll
    for (int i = 0; i < 8; i++) {
        float2 p0 = unpk(acc[i][0]), p1 = unpk(acc[i][1]);
        float4 o4 = make_float4(p0.x, p0.y, p1.x, p1.y);
        int s = i0 + ty * 8 + i;
        *(float4*)(outp + ((size_t)b * SS + s) * HH + h * HD + tx * 4) = o4;
    }
}

// ---------------------------------------------------------------------------
extern "C" void kernel_launch(void* const* d_in, const int* in_sizes, int n_in,
                              void* d_out, int out_size)
{
    const float* query = (const float*)d_in[0];
    const float* key   = (const float*)d_in[1];
    const float* value = (const float*)d_in[2];
    const unsigned char* mask = (const unsigned char*)d_in[3];
    const float* Wq = (const float*)d_in[4];
    const float* bq = (const float*)d_in[5];
    const float* Wk = (const float*)d_in[6];
    const float* bk = (const float*)d_in[7];
    const float* Wv = (const float*)d_in[8];
    const float* bv = (const float*)d_in[9];

    float* outp = (float*)d_out;                        // [B,S,H]
    float* wts  = outp + (size_t)BB * SS * HH;          // [B,h,S,S]

    float *gq, *gk, *gv, *gkt, *gwt;
    cudaGetSymbolAddress((void**)&gq, g_q);
    cudaGetSymbolAddress((void**)&gk, g_k);
    cudaGetSymbolAddress((void**)&gv, g_v);
    cudaGetSymbolAddress((void**)&gkt, g_kt);
    cudaGetSymbolAddress((void**)&gwt, g_wt);

    cudaFuncSetAttribute(score_kernel, cudaFuncAttributeMaxDynamicSharedMemorySize,
                         SCORE_SMEM);
    cudaFuncSetAttribute(pv_kernel, cudaFuncAttributeMaxDynamicSharedMemorySize,
                         PV_SMEM);

    dim3 tb(32, 8);

    transpose_w3<<<dim3(32, 32, 3), tb>>>(Wq, Wk, Wv, gwt);

    dim3 pgrid(HH / 128, NROWS / 128, 3);
    proj_kernel<<<pgrid, 256>>>(query, key, value, gwt, bq, bk, bv, gq, gk, gv);

    dim3 tkgrid(SS / 32, HD / 32, BH);
    transpose_k<<<tkgrid, tb>>>(gk, gkt);

    dim3 sgrid(SS / 128 / 4, SS / 128, BH);
    score_kernel<<<sgrid, 256, SCORE_SMEM>>>(wts);

    softmax_kernel<<<(BH * SS) / 8, 256>>>(mask, wts);

    dim3 vgrid(SS / 128, BH);
    pv_kernel<<<vgrid, 256, PV_SMEM>>>(wts, outp);
}